// round 10
// baseline (speedup 1.0000x reference)
#include <cuda_runtime.h>
#include <cstdint>

// ---------------------------------------------------------------------------
// MQNet round 10: BITWISE-R1 numerics, pipelined implementation.
//   Evidence: argmax margins ~1e-6 => any accumulation-order change re-rolls
//   a coin on one action flip (R5/R6/R8/R9 all flipped; R1 passed).
//   Every C element here is the same strictly k-ordered FFMA chain as R1's
//   sgemm => bitwise-identical output, but with register-prefetch +
//   double-buffered SMEM + one barrier per k-tile to fix R1's latency bind
//   (fma 43.6%, occ 20.9%).
// ---------------------------------------------------------------------------

#define NN 8192
#define HH 512
#define H3 1536
#define BS 20

// ------------------------- device scratch (no mallocs) ---------------------
__device__ float g_xw[NN * HH];
__device__ float g_feats[NN * HH];
__device__ float g_gcn[NN * HH];
__device__ float g_gi[(size_t)NN * H3];
__device__ float g_h[HH];
__device__ float g_gh[H3];
__device__ unsigned long long g_key;
__device__ int g_mask[NN];

// ------------------------- helpers -----------------------------------------
__device__ __forceinline__ unsigned ford(float f) {
    unsigned u = __float_as_uint(f);
    return (u & 0x80000000u) ? ~u : (u | 0x80000000u);
}
__device__ __forceinline__ float forddec(unsigned u) {
    return (u & 0x80000000u) ? __uint_as_float(u & 0x7FFFFFFFu)
                             : __uint_as_float(~u);
}
__device__ __forceinline__ float sigf(float x) {
    return 1.0f / (1.0f + __expf(-x));
}
__device__ __forceinline__ float tanh_f(float x) {
    return 1.0f - 2.0f / (1.0f + __expf(2.0f * x));
}

// ------------------------- pipelined fp32 SGEMM (bitwise == R1) -------------
// C[M,N] = A[M,K] * op(B) (+bias) (relu). Per-element strictly k-ordered FFMA
// chain — identical arithmetic to the R1 kernel that passed.
template <bool BT, int EPI>  // EPI: 0 none, 1 +bias, 2 +bias & relu
__global__ void __launch_bounds__(256, 2)
sgemm2(const float* __restrict__ A, const float* __restrict__ B,
       const float* __restrict__ bias, float* __restrict__ C,
       int M, int N, int K) {
    const int BK = 16;
    __shared__ float As[2][BK][128];
    __shared__ float Bs[2][BK][128];

    const int t = threadIdx.x;
    const int tx = t & 15;
    const int ty = t >> 4;
    const int m0 = blockIdx.y * 128;
    const int n0 = blockIdx.x * 128;

    float acc[8][8];
#pragma unroll
    for (int i = 0; i < 8; i++)
#pragma unroll
        for (int j = 0; j < 8; j++) acc[i][j] = 0.f;

    const float* Ab = A + (size_t)m0 * K;
    const int ntiles = K / BK;

    // ---------------- prologue: tile 0 -> buffer 0 ---------------------------
#pragma unroll
    for (int i = 0; i < 2; i++) {
        int lin = t + i * 256;
        {
            int row = lin >> 2, kc = (lin & 3) * 4;
            float4 v = *reinterpret_cast<const float4*>(
                Ab + (size_t)row * K + kc);
            As[0][kc + 0][row] = v.x;
            As[0][kc + 1][row] = v.y;
            As[0][kc + 2][row] = v.z;
            As[0][kc + 3][row] = v.w;
        }
        if (!BT) {
            int row = lin >> 5, c = (lin & 31) * 4;
            float4 v = *reinterpret_cast<const float4*>(
                B + (size_t)row * N + n0 + c);
            *reinterpret_cast<float4*>(&Bs[0][row][c]) = v;
        } else {
            int row = lin >> 2, kc = (lin & 3) * 4;
            float4 v = *reinterpret_cast<const float4*>(
                B + (size_t)(n0 + row) * K + kc);
            Bs[0][kc + 0][row] = v.x;
            Bs[0][kc + 1][row] = v.y;
            Bs[0][kc + 2][row] = v.z;
            Bs[0][kc + 3][row] = v.w;
        }
    }
    __syncthreads();

    int buf = 0;
    for (int kt = 0; kt < ntiles; kt++) {
        // -------- prefetch next tile into registers --------
        float4 pa[2], pb[2];
        const bool has_next = (kt + 1) < ntiles;
        const int k0n = (kt + 1) * BK;
        if (has_next) {
#pragma unroll
            for (int i = 0; i < 2; i++) {
                int lin = t + i * 256;
                {
                    int row = lin >> 2, kc = (lin & 3) * 4;
                    pa[i] = *reinterpret_cast<const float4*>(
                        Ab + (size_t)row * K + k0n + kc);
                }
                if (!BT) {
                    int row = lin >> 5, c = (lin & 31) * 4;
                    pb[i] = *reinterpret_cast<const float4*>(
                        B + (size_t)(k0n + row) * N + n0 + c);
                } else {
                    int row = lin >> 2, kc = (lin & 3) * 4;
                    pb[i] = *reinterpret_cast<const float4*>(
                        B + (size_t)(n0 + row) * K + k0n + kc);
                }
            }
        }

        // -------- compute on buf (identical FFMA order to R1) --------
#pragma unroll
        for (int kk = 0; kk < BK; kk++) {
            float ra[8], rb[8];
#pragma unroll
            for (int i = 0; i < 8; i++) ra[i] = As[buf][kk][ty * 8 + i];
#pragma unroll
            for (int j = 0; j < 8; j++) rb[j] = Bs[buf][kk][tx * 8 + j];
#pragma unroll
            for (int i = 0; i < 8; i++)
#pragma unroll
                for (int j = 0; j < 8; j++) acc[i][j] += ra[i] * rb[j];
        }

        // -------- store prefetched tile into other buffer --------
        if (has_next) {
            int s = buf ^ 1;
#pragma unroll
            for (int i = 0; i < 2; i++) {
                int lin = t + i * 256;
                {
                    int row = lin >> 2, kc = (lin & 3) * 4;
                    As[s][kc + 0][row] = pa[i].x;
                    As[s][kc + 1][row] = pa[i].y;
                    As[s][kc + 2][row] = pa[i].z;
                    As[s][kc + 3][row] = pa[i].w;
                }
                if (!BT) {
                    int row = lin >> 5, c = (lin & 31) * 4;
                    *reinterpret_cast<float4*>(&Bs[s][row][c]) = pb[i];
                } else {
                    int row = lin >> 2, kc = (lin & 3) * 4;
                    Bs[s][kc + 0][row] = pb[i].x;
                    Bs[s][kc + 1][row] = pb[i].y;
                    Bs[s][kc + 2][row] = pb[i].z;
                    Bs[s][kc + 3][row] = pb[i].w;
                }
            }
        }
        __syncthreads();
        buf ^= 1;
    }

    // ---------------- epilogue (identical arithmetic to R1) ------------------
#pragma unroll
    for (int i = 0; i < 8; i++) {
        int m = m0 + ty * 8 + i;
#pragma unroll
        for (int j = 0; j < 8; j++) {
            int n = n0 + tx * 8 + j;
            float v = acc[i][j];
            if (EPI >= 1) v += bias[n];
            if (EPI == 2) v = fmaxf(v, 0.f);
            C[(size_t)m * N + n] = v;
        }
    }
}

// ------------------------- init: mask=1, key=0 ------------------------------
__global__ void init_kernel() {
    int i = blockIdx.x * blockDim.x + threadIdx.x;
    if (i < NN) g_mask[i] = 1;
    if (i == 0) g_key = 0ull;
}

// ------------------------- step-0 GEMV + argmax (verbatim R1) ---------------
__global__ void __launch_bounds__(256)
gemv_argmax_kernel(const float* __restrict__ w, const float* __restrict__ b) {
    __shared__ float sw[HH];
    __shared__ unsigned long long skey[8];
    int t = threadIdx.x;
    for (int j = t; j < HH; j += 256) sw[j] = w[j];
    __syncthreads();

    int wid = t >> 5, lane = t & 31;
    int i = blockIdx.x * 8 + wid;
    const float* row = g_gcn + (size_t)i * HH;
    float acc = 0.f;
#pragma unroll 4
    for (int jj = 0; jj < 16; jj++) {
        int j = lane + jj * 32;
        acc += row[j] * sw[j];
    }
#pragma unroll
    for (int o = 16; o; o >>= 1) acc += __shfl_down_sync(0xffffffffu, acc, o);
    if (lane == 0) {
        float v = acc + b[0];
        skey[wid] = ((unsigned long long)ford(v) << 32) |
                    (0xFFFFFFFFu - (unsigned)i);
    }
    __syncthreads();
    if (t == 0) {
        unsigned long long best = skey[0];
#pragma unroll
        for (int w2 = 1; w2 < 8; w2++) best = best > skey[w2] ? best : skey[w2];
        atomicMax(&g_key, best);
    }
}

// ------------------------- gh = h @ W_hh^T + b_hh (verbatim R1) -------------
__global__ void __launch_bounds__(256)
gh_kernel(const float* __restrict__ Whh, const float* __restrict__ bhh) {
    __shared__ float sh[HH];
    int t = threadIdx.x;
    for (int j = t; j < HH; j += 256) sh[j] = g_h[j];
    __syncthreads();
    int wid = t >> 5, lane = t & 31;
    int o = blockIdx.x * 8 + wid;
    const float* wr = Whh + (size_t)o * HH;
    float acc = 0.f;
#pragma unroll 4
    for (int jj = 0; jj < 16; jj++) {
        int j = lane + jj * 32;
        acc += wr[j] * sh[j];
    }
#pragma unroll
    for (int off = 16; off; off >>= 1)
        acc += __shfl_down_sync(0xffffffffu, acc, off);
    if (lane == 0) g_gh[o] = acc + bhh[o];
}

// ------------------------- GRU elementwise + vals + argmax (verbatim R1) ----
__global__ void __launch_bounds__(256)
gru_vals_kernel(const float* __restrict__ w2, const float* __restrict__ b2) {
    __shared__ float sgh[H3];
    __shared__ float sh[HH];
    __shared__ float sw[HH];
    __shared__ unsigned long long skey[8];
    int t = threadIdx.x;
    for (int j = t; j < H3; j += 256) sgh[j] = g_gh[j];
    for (int j = t; j < HH; j += 256) {
        sh[j] = g_h[j];
        sw[j] = w2[j];
    }
    __syncthreads();

    int wid = t >> 5, lane = t & 31;
    int i = blockIdx.x * 8 + wid;
    unsigned long long key = 0ull;
    if (g_mask[i]) {
        const float* gi = g_gi + (size_t)i * H3;
        float acc = 0.f;
#pragma unroll 4
        for (int jj = 0; jj < 16; jj++) {
            int j = lane + jj * 32;
            float r = sigf(gi[j] + sgh[j]);
            float z = sigf(gi[j + 512] + sgh[j + 512]);
            float ng = tanh_f(gi[j + 1024] + r * sgh[j + 1024]);
            float rnn = (1.f - z) * ng + z * sh[j];
            acc += sw[j] * rnn;
        }
#pragma unroll
        for (int o = 16; o; o >>= 1) acc += __shfl_down_sync(0xffffffffu, acc, o);
        if (lane == 0) {
            float v = acc + b2[0];
            key = ((unsigned long long)ford(v) << 32) |
                  (0xFFFFFFFFu - (unsigned)i);
        }
    }
    if (lane == 0) skey[wid] = key;
    __syncthreads();
    if (t == 0) {
        unsigned long long best = skey[0];
#pragma unroll
        for (int w = 1; w < 8; w++) best = best > skey[w] ? best : skey[w];
        atomicMax(&g_key, best);
    }
}

// ------------------------- select (verbatim R1) -----------------------------
__global__ void __launch_bounds__(512)
select_kernel(float* __restrict__ out, int step, int first) {
    __shared__ int sidx;
    int t = threadIdx.x;
    if (t == 0) {
        unsigned long long key = g_key;
        int idx = (int)(0xFFFFFFFFu - (unsigned)(key & 0xFFFFFFFFull));
        float v = forddec((unsigned)(key >> 32));
        out[step] = (float)idx;
        out[BS + step] = v;
        g_mask[idx] = 0;
        g_key = 0ull;
        sidx = idx;
    }
    __syncthreads();
    int idx = sidx;
    int j = t;
    if (first) {
        g_h[j] = g_gcn[(size_t)idx * HH + j];
    } else {
        const float* gi = g_gi + (size_t)idx * H3;
        float r = sigf(gi[j] + g_gh[j]);
        float z = sigf(gi[j + 512] + g_gh[j + 512]);
        float ng = tanh_f(gi[j + 1024] + r * g_gh[j + 1024]);
        g_h[j] = (1.f - z) * ng + z * g_h[j];
    }
}

// ------------------------- launch ------------------------------------------
extern "C" void kernel_launch(void* const* d_in, const int* in_sizes, int n_in,
                              void* d_out, int out_size) {
    (void)in_sizes; (void)n_in; (void)out_size;
    const float* state  = (const float*)d_in[0];
    const float* adj    = (const float*)d_in[1];
    const float* W1     = (const float*)d_in[3];
    const float* b1     = (const float*)d_in[4];
    const float* W2     = (const float*)d_in[5];
    const float* b2     = (const float*)d_in[6];
    const float* w_out1 = (const float*)d_in[7];
    const float* b_out1 = (const float*)d_in[8];
    const float* w_out2 = (const float*)d_in[9];
    const float* b_out2 = (const float*)d_in[10];
    const float* W_ih   = (const float*)d_in[11];
    const float* W_hh   = (const float*)d_in[12];
    const float* b_ih   = (const float*)d_in[13];
    const float* b_hh   = (const float*)d_in[14];
    float* out = (float*)d_out;

    float *xw, *feats, *gcn, *gi;
    cudaGetSymbolAddress((void**)&xw, g_xw);
    cudaGetSymbolAddress((void**)&feats, g_feats);
    cudaGetSymbolAddress((void**)&gcn, g_gcn);
    cudaGetSymbolAddress((void**)&gi, g_gi);

    dim3 blk(256);

    init_kernel<<<(NN + 255) / 256, 256>>>();

    // G1: XW = state @ W1
    sgemm2<false, 0><<<dim3(HH / 128, NN / 128), blk>>>(
        state, W1, nullptr, xw, NN, HH, HH);
    // G2: feats = relu(adj @ XW + b1)
    sgemm2<false, 2><<<dim3(HH / 128, NN / 128), blk>>>(
        adj, xw, b1, feats, NN, HH, NN);
    // G3: XW = feats @ W2
    sgemm2<false, 0><<<dim3(HH / 128, NN / 128), blk>>>(
        feats, W2, nullptr, xw, NN, HH, HH);
    // G4: gcn = relu(adj @ XW + b2)
    sgemm2<false, 2><<<dim3(HH / 128, NN / 128), blk>>>(
        adj, xw, b2, gcn, NN, HH, NN);
    // G5: gi = gcn @ W_ih^T + b_ih
    sgemm2<true, 1><<<dim3(H3 / 128, NN / 128), blk>>>(
        gcn, W_ih, b_ih, gi, NN, H3, HH);

    // step 0
    gemv_argmax_kernel<<<NN / 8, blk>>>(w_out1, b_out1);
    select_kernel<<<1, 512>>>(out, 0, 1);

    // steps 1..19
    for (int t = 1; t < BS; t++) {
        gh_kernel<<<H3 / 8, blk>>>(W_hh, b_hh);
        gru_vals_kernel<<<NN / 8, blk>>>(w_out2, b_out2);
        select_kernel<<<1, 512>>>(out, t, 0);
    }
}